// round 5
// baseline (speedup 1.0000x reference)
#include <cuda_runtime.h>
#include <cstdint>
#include <cstddef>

#define Bb   128
#define Tt   196
#define TT   392      // 2T
#define ENC  1024
#define DEC  512
#define Vv   98
#define Mm   294

// ---- scratch (no allocations allowed) ----
__device__ int            g_destTok[Bb * Vv];      // gemm row -> token index
__device__ unsigned char  g_vis[Bb * TT];          // 1 if (b,t) visible

__device__ __forceinline__ uint32_t s2u(const void* p) {
    uint32_t a;
    asm("{ .reg .u64 t; cvta.to.shared.u64 t, %1; cvt.u32.u64 %0, t; }"
        : "=r"(a) : "l"(p));
    return a;
}

#define LDSM_X4(r, addr)                                                       \
    asm volatile("ldmatrix.sync.aligned.m8n8.x4.shared.b16 {%0,%1,%2,%3}, [%4];"\
        : "=r"((r)[0]), "=r"((r)[1]), "=r"((r)[2]), "=r"((r)[3]) : "r"(addr))

#define MMA_TF32(C, A, Bf)                                                     \
    asm volatile(                                                              \
        "mma.sync.aligned.m16n8k8.row.col.f32.tf32.tf32.f32 "                  \
        "{%0,%1,%2,%3}, {%4,%5,%6,%7}, {%8,%9}, {%0,%1,%2,%3};\n"              \
        : "+f"((C)[0]), "+f"((C)[1]), "+f"((C)[2]), "+f"((C)[3])               \
        : "r"((A)[0]), "r"((A)[1]), "r"((A)[2]), "r"((A)[3]),                  \
          "r"((Bf)[0]), "r"((Bf)[1]))

// ============================================================
// Kernel 1: per-row visible ids (ascending complement).
// masked_ids dtype (int32/int64) detected inline from row 0.
// ============================================================
__global__ void __launch_bounds__(512)
visids_kernel(const void* __restrict__ mids_raw) {
    __shared__ unsigned char vis[TT];
    __shared__ int scan[512];
    const int b = blockIdx.x;
    const int t = threadIdx.x;

    bool bad = false;
    {
        const long long* p = (const long long*)mids_raw;
        for (int j = t; j < 147; j += 512) {
            long long v = p[j];
            if (v < 0 || v >= TT) bad = true;
        }
    }
    const int ids64 = __syncthreads_or(bad) ? 0 : 1;

    if (t < TT) vis[t] = 1;
    __syncthreads();
    if (ids64) {
        const long long* mids = (const long long*)mids_raw + (long long)b * Mm;
        for (int j = t; j < Mm; j += 512) vis[(int)mids[j]] = 0;
    } else {
        const int* mids = (const int*)mids_raw + b * Mm;
        for (int j = t; j < Mm; j += 512) vis[mids[j]] = 0;
    }
    __syncthreads();

    const int f = (t < TT) ? (int)vis[t] : 0;
    scan[t] = f;
    __syncthreads();
    #pragma unroll
    for (int off = 1; off < 512; off <<= 1) {
        int v = scan[t];
        int add = (t >= off) ? scan[t - off] : 0;
        __syncthreads();
        scan[t] = v + add;
        __syncthreads();
    }
    if (t < TT) {
        g_vis[b * TT + t] = (unsigned char)f;
        if (f) g_destTok[b * Vv + (scan[t] - 1)] = t;
    }
}

// ============================================================
// Kernel 2 (fused): tf32 mma.sync GEMM (CTAs 0..391) + fill (392..491)
//   GEMM: BM=128 BN=128 BK=32, 4 warps, warp tile 64x64 (2x2 grid):
//   A and B smem each read only 2x (vs 2x/4x before), cp.async 3-stage,
//   ldmatrix.x4 frags, raw-fp32-as-tf32, fused scatter epilogue.
// ============================================================
#define GEMMB   392                    // 98 m-blocks x 4 n-blocks
#define FILLB   100
#define NTHR    128
#define BM      128
#define BN      128
#define BK      32
#define NCHUNK  (ENC / BK)             // 32
#define A_BYTES (BM * BK * 4)          // 16 KB
#define B_BYTES (BN * BK * 4)          // 16 KB
#define STAGE   (A_BYTES + B_BYTES)    // 32 KB
#define NSTAGE  3
#define SMEM_DYN (NSTAGE * STAGE)      // 96 KB

__device__ __forceinline__ void load_stage(uint32_t smem_base, int s, int kt,
                                           const float* __restrict__ x,
                                           const float* __restrict__ W,
                                           int m0, int n0, int tid) {
    const uint32_t abase = smem_base + s * STAGE;
    const uint32_t bbase = abase + A_BYTES;
    const float* xs = x + (size_t)m0 * ENC + kt * BK;
    const float* ws = W + (size_t)n0 * ENC + kt * BK;
    // A: 128 rows x 8 chunks = 1024 chunks; B same. 16 cp.async / thread.
    #pragma unroll
    for (int i = 0; i < 8; i++) {
        int c = tid + i * NTHR;
        int r = c >> 3, u = c & 7;
        uint32_t dst = abase + r * 128 + ((u ^ (r & 7)) << 4);
        const float* src = xs + (size_t)r * ENC + u * 4;
        asm volatile("cp.async.cg.shared.global [%0], [%1], 16;"
                     :: "r"(dst), "l"(src));
    }
    #pragma unroll
    for (int i = 0; i < 8; i++) {
        int c = tid + i * NTHR;
        int r = c >> 3, u = c & 7;
        uint32_t dst = bbase + r * 128 + ((u ^ (r & 7)) << 4);
        const float* src = ws + (size_t)r * ENC + u * 4;
        asm volatile("cp.async.cg.shared.global [%0], [%1], 16;"
                     :: "r"(dst), "l"(src));
    }
    asm volatile("cp.async.commit_group;" ::: "memory");
}

__global__ void __launch_bounds__(NTHR, 2)
fused_kernel(const float* __restrict__ x,          // [12544,1024]
             const float* __restrict__ W,          // [512,1024]
             const float* __restrict__ bias,       // [512]
             const float* __restrict__ mask_token, // [512]
             const float* __restrict__ pos,        // [392,512]
             const float* __restrict__ ve,         // [2,512]
             float* __restrict__ out) {            // [128,392,512]
    const int tid  = threadIdx.x;
    const int wid  = tid >> 5;
    const int lane = tid & 31;

    if (blockIdx.x >= GEMMB) {
        // ---------------- fill path ----------------
        const int wg = (blockIdx.x - GEMMB) * 4 + wid;   // 0..399
        float4 mt[4], ves[2][4];
        const float4* mt4  = (const float4*)mask_token;
        const float4* ve4  = (const float4*)ve;
        const float4* pos4 = (const float4*)pos;
        float4* out4 = (float4*)out;
        #pragma unroll
        for (int j = 0; j < 4; j++) {
            mt[j]     = mt4[lane + 32 * j];
            ves[0][j] = ve4[lane + 32 * j];
            ves[1][j] = ve4[128 + lane + 32 * j];
        }
        for (int row = wg; row < Bb * TT; row += FILLB * 4) {
            if (g_vis[row]) continue;
            const int tok = row % TT;
            const int vs  = (tok >= Tt) ? 1 : 0;
            const float4* prow = pos4 + tok * 128;
            float4* orow = out4 + (size_t)row * 128;
            #pragma unroll
            for (int j = 0; j < 4; j++) {
                const int d4 = lane + 32 * j;
                float4 pp = prow[d4];
                float4 o;
                o.x = mt[j].x + pp.x + ves[vs][j].x;
                o.y = mt[j].y + pp.y + ves[vs][j].y;
                o.z = mt[j].z + pp.z + ves[vs][j].z;
                o.w = mt[j].w + pp.w + ves[vs][j].w;
                orow[d4] = o;
            }
        }
        return;
    }

    // ---------------- GEMM path ----------------
    extern __shared__ __align__(1024) char smem[];
    const uint32_t smem_base = s2u(smem);

    const int mblk = blockIdx.x >> 2;
    const int nblk = blockIdx.x & 3;
    const int m0 = mblk * BM;
    const int n0 = nblk * BN;
    const int warpM = wid & 1;           // 2 warps over M (64 rows each)
    const int warpN = wid >> 1;          // 2 warps over N (64 cols each)

    // A: row = warpM*64 + mt*16 + ((lane>>3)&1)*8 + (lane&7); chunk-half = lane>>4
    const int aRow0 = warpM * 64 + ((lane >> 3) & 1) * 8 + (lane & 7);
    const int aChalf = lane >> 4;
    uint32_t aOff[4];
    int aRx[4];
    #pragma unroll
    for (int mt = 0; mt < 4; mt++) {
        int r = aRow0 + mt * 16;
        aOff[mt] = (uint32_t)(r * 128);
        aRx[mt]  = r & 7;
    }
    // B: row = warpN*64 + j*16 + (lane>>4)*8 + (lane&7); chunk-half = (lane>>3)&1
    const int bRow0 = warpN * 64 + (lane >> 4) * 8 + (lane & 7);
    const int bChalf = (lane >> 3) & 1;
    uint32_t bOff[4];
    int bRx[4];
    #pragma unroll
    for (int j = 0; j < 4; j++) {
        int r = bRow0 + j * 16;
        bOff[j] = (uint32_t)(r * 128);
        bRx[j]  = r & 7;
    }

    float c[4][8][4];
    #pragma unroll
    for (int i = 0; i < 4; i++)
        #pragma unroll
        for (int j = 0; j < 8; j++)
            #pragma unroll
            for (int k = 0; k < 4; k++) c[i][j][k] = 0.f;

    load_stage(smem_base, 0, 0, x, W, m0, n0, tid);
    load_stage(smem_base, 1, 1, x, W, m0, n0, tid);

    #pragma unroll 1
    for (int kt = 0; kt < NCHUNK; ++kt) {
        if (kt + 2 < NCHUNK) {
            load_stage(smem_base, (kt + 2) % NSTAGE, kt + 2, x, W, m0, n0, tid);
            asm volatile("cp.async.wait_group 2;" ::: "memory");
        } else if (kt + 1 < NCHUNK) {
            asm volatile("cp.async.wait_group 1;" ::: "memory");
        } else {
            asm volatile("cp.async.wait_group 0;" ::: "memory");
        }
        __syncthreads();

        const uint32_t Ab = smem_base + (kt % NSTAGE) * STAGE;
        const uint32_t Bbs = Ab + A_BYTES;
        #pragma unroll
        for (int ks = 0; ks < 4; ks++) {
            unsigned a[4][4], b[8][2];
            #pragma unroll
            for (int mt = 0; mt < 4; mt++) {
                uint32_t ad = Ab + aOff[mt] +
                              (uint32_t)(((2 * ks + aChalf) ^ aRx[mt]) << 4);
                LDSM_X4(a[mt], ad);
            }
            #pragma unroll
            for (int j = 0; j < 4; j++) {
                uint32_t bd = Bbs + bOff[j] +
                              (uint32_t)(((2 * ks + bChalf) ^ bRx[j]) << 4);
                LDSM_X4((&b[2 * j][0]), bd);   // fills b[2j][0..1], b[2j+1][0..1]
            }
            #pragma unroll
            for (int mt = 0; mt < 4; mt++)
                #pragma unroll
                for (int ni = 0; ni < 8; ni++)
                    MMA_TF32(c[mt][ni], a[mt], b[ni]);
        }
        __syncthreads();
    }

    // epilogue: scatter with bias + pos + view fused
    const int group = lane >> 2;
    const int tig   = lane & 3;
    const int m_base = m0 + warpM * 64;
    const int n_base = n0 + warpN * 64;
    #pragma unroll
    for (int mt = 0; mt < 4; mt++) {
        #pragma unroll
        for (int rs = 0; rs < 2; rs++) {
            const int m   = m_base + mt * 16 + rs * 8 + group;
            const int bb  = m / Vv;
            const int tok = g_destTok[m];
            const float* prow = pos + tok * DEC;
            const float* vrow = ve + (tok >= Tt ? DEC : 0);
            float* optr = out + ((size_t)bb * TT + tok) * DEC;
            #pragma unroll
            for (int ni = 0; ni < 8; ni++) {
                const int n = n_base + ni * 8 + 2 * tig;
                float2 bp = *(const float2*)(bias + n);
                float2 pp = *(const float2*)(prow + n);
                float2 vv = *(const float2*)(vrow + n);
                float2 r;
                r.x = c[mt][ni][rs * 2 + 0] + bp.x + pp.x + vv.x;
                r.y = c[mt][ni][rs * 2 + 1] + bp.y + pp.y + vv.y;
                *(float2*)(optr + n) = r;
            }
        }
    }
}

// ============================================================
// launch
// ============================================================
extern "C" void kernel_launch(void* const* d_in, const int* in_sizes, int n_in,
                              void* d_out, int out_size) {
    const float* x          = (const float*)d_in[0];
    const void*  masked_ids = d_in[1];
    const float* W          = (const float*)d_in[2];
    const float* bias       = (const float*)d_in[3];
    const float* mask_token = (const float*)d_in[4];
    const float* pos        = (const float*)d_in[5];
    const float* ve         = (const float*)d_in[6];
    float* out = (float*)d_out;

    cudaFuncSetAttribute(fused_kernel,
                         cudaFuncAttributeMaxDynamicSharedMemorySize, SMEM_DYN);

    visids_kernel<<<Bb, 512>>>(masked_ids);
    fused_kernel<<<GEMMB + FILLB, NTHR, SMEM_DYN>>>(
        x, W, bias, mask_token, pos, ve, out);
}

// round 6
// speedup vs baseline: 1.0585x; 1.0585x over previous
#include <cuda_runtime.h>
#include <cstdint>
#include <cstddef>

#define Bb   128
#define Tt   196
#define TT   392      // 2T
#define ENC  1024
#define DEC  512
#define Vv   98
#define Mm   294

// ---- scratch (no allocations allowed) ----
__device__ int            g_destTok[Bb * Vv];      // gemm row -> token index
__device__ unsigned char  g_vis[Bb * TT];          // 1 if (b,t) visible

__device__ __forceinline__ uint32_t s2u(const void* p) {
    uint32_t a;
    asm("{ .reg .u64 t; cvta.to.shared.u64 t, %1; cvt.u32.u64 %0, t; }"
        : "=r"(a) : "l"(p));
    return a;
}

#define LDSM_X4(r, addr)                                                       \
    asm volatile("ldmatrix.sync.aligned.m8n8.x4.shared.b16 {%0,%1,%2,%3}, [%4];"\
        : "=r"((r)[0]), "=r"((r)[1]), "=r"((r)[2]), "=r"((r)[3]) : "r"(addr))

#define MMA_TF32(C, A, Bf)                                                     \
    asm volatile(                                                              \
        "mma.sync.aligned.m16n8k8.row.col.f32.tf32.tf32.f32 "                  \
        "{%0,%1,%2,%3}, {%4,%5,%6,%7}, {%8,%9}, {%0,%1,%2,%3};\n"              \
        : "+f"((C)[0]), "+f"((C)[1]), "+f"((C)[2]), "+f"((C)[3])               \
        : "r"((A)[0]), "r"((A)[1]), "r"((A)[2]), "r"((A)[3]),                  \
          "r"((Bf)[0]), "r"((Bf)[1]))

// ============================================================
// Kernel 1: per-row visible ids (ascending complement).
// masked_ids dtype (int32/int64) detected inline from row 0.
// ============================================================
__global__ void __launch_bounds__(512)
visids_kernel(const void* __restrict__ mids_raw) {
    __shared__ unsigned char vis[TT];
    __shared__ int scan[512];
    const int b = blockIdx.x;
    const int t = threadIdx.x;

    bool bad = false;
    {
        const long long* p = (const long long*)mids_raw;
        for (int j = t; j < 147; j += 512) {
            long long v = p[j];
            if (v < 0 || v >= TT) bad = true;
        }
    }
    const int ids64 = __syncthreads_or(bad) ? 0 : 1;

    if (t < TT) vis[t] = 1;
    __syncthreads();
    if (ids64) {
        const long long* mids = (const long long*)mids_raw + (long long)b * Mm;
        for (int j = t; j < Mm; j += 512) vis[(int)mids[j]] = 0;
    } else {
        const int* mids = (const int*)mids_raw + b * Mm;
        for (int j = t; j < Mm; j += 512) vis[mids[j]] = 0;
    }
    __syncthreads();

    const int f = (t < TT) ? (int)vis[t] : 0;
    scan[t] = f;
    __syncthreads();
    #pragma unroll
    for (int off = 1; off < 512; off <<= 1) {
        int v = scan[t];
        int add = (t >= off) ? scan[t - off] : 0;
        __syncthreads();
        scan[t] = v + add;
        __syncthreads();
    }
    if (t < TT) {
        g_vis[b * TT + t] = (unsigned char)f;
        if (f) g_destTok[b * Vv + (scan[t] - 1)] = t;
    }
}

// ============================================================
// Kernel 2 (fused): tf32 mma.sync GEMM (CTAs 0..391) + fill (392..443)
//   Single-wave design: 3 CTAs/SM (2-stage 64KB smem, <=170 regs),
//   4 warps, warp tile 64x64, one __syncthreads per K-chunk,
//   raw-fp32-as-tf32 via ldmatrix, fused scatter epilogue.
// ============================================================
#define GEMMB   392                    // 98 m-blocks x 4 n-blocks
#define FILLB   52
#define NTHR    128
#define BM      128
#define BN      128
#define BK      32
#define NCHUNK  (ENC / BK)             // 32
#define A_BYTES (BM * BK * 4)          // 16 KB
#define B_BYTES (BN * BK * 4)          // 16 KB
#define STAGE   (A_BYTES + B_BYTES)    // 32 KB
#define NSTAGE  2
#define SMEM_DYN (NSTAGE * STAGE)      // 64 KB

__device__ __forceinline__ void load_stage(uint32_t smem_base, int s, int kt,
                                           const float* __restrict__ x,
                                           const float* __restrict__ W,
                                           int m0, int n0, int tid) {
    const uint32_t abase = smem_base + s * STAGE;
    const uint32_t bbase = abase + A_BYTES;
    const float* xs = x + (size_t)m0 * ENC + kt * BK;
    const float* ws = W + (size_t)n0 * ENC + kt * BK;
    const int r0 = tid >> 3, u = tid & 7;
    #pragma unroll
    for (int i = 0; i < 8; i++) {
        int r = r0 + i * 16;
        uint32_t dst = abase + r * 128 + ((u ^ (r & 7)) << 4);
        const float* src = xs + (size_t)r * ENC + u * 4;
        asm volatile("cp.async.cg.shared.global [%0], [%1], 16;"
                     :: "r"(dst), "l"(src));
    }
    #pragma unroll
    for (int i = 0; i < 8; i++) {
        int r = r0 + i * 16;
        uint32_t dst = bbase + r * 128 + ((u ^ (r & 7)) << 4);
        const float* src = ws + (size_t)r * ENC + u * 4;
        asm volatile("cp.async.cg.shared.global [%0], [%1], 16;"
                     :: "r"(dst), "l"(src));
    }
    asm volatile("cp.async.commit_group;" ::: "memory");
}

__global__ void __launch_bounds__(NTHR, 3)
fused_kernel(const float* __restrict__ x,          // [12544,1024]
             const float* __restrict__ W,          // [512,1024]
             const float* __restrict__ bias,       // [512]
             const float* __restrict__ mask_token, // [512]
             const float* __restrict__ pos,        // [392,512]
             const float* __restrict__ ve,         // [2,512]
             float* __restrict__ out) {            // [128,392,512]
    const int tid  = threadIdx.x;
    const int wid  = tid >> 5;
    const int lane = tid & 31;

    if (blockIdx.x >= GEMMB) {
        // ---------------- fill path ----------------
        const int wg = (blockIdx.x - GEMMB) * 4 + wid;   // 0..207
        float4 mt[4], ves[2][4];
        const float4* mt4  = (const float4*)mask_token;
        const float4* ve4  = (const float4*)ve;
        const float4* pos4 = (const float4*)pos;
        float4* out4 = (float4*)out;
        #pragma unroll
        for (int j = 0; j < 4; j++) {
            mt[j]     = mt4[lane + 32 * j];
            ves[0][j] = ve4[lane + 32 * j];
            ves[1][j] = ve4[128 + lane + 32 * j];
        }
        for (int row = wg; row < Bb * TT; row += FILLB * 4) {
            if (g_vis[row]) continue;
            const int tok = row % TT;
            const int vs  = (tok >= Tt) ? 1 : 0;
            const float4* prow = pos4 + tok * 128;
            float4* orow = out4 + (size_t)row * 128;
            #pragma unroll
            for (int j = 0; j < 4; j++) {
                const int d4 = lane + 32 * j;
                float4 pp = prow[d4];
                float4 o;
                o.x = mt[j].x + pp.x + ves[vs][j].x;
                o.y = mt[j].y + pp.y + ves[vs][j].y;
                o.z = mt[j].z + pp.z + ves[vs][j].z;
                o.w = mt[j].w + pp.w + ves[vs][j].w;
                orow[d4] = o;
            }
        }
        return;
    }

    // ---------------- GEMM path ----------------
    extern __shared__ __align__(1024) char smem[];
    const uint32_t smem_base = s2u(smem);

    const int mblk = blockIdx.x >> 2;
    const int nblk = blockIdx.x & 3;
    const int m0 = mblk * BM;
    const int n0 = nblk * BN;
    const int warpM = wid & 1;           // 2 warps over M (64 rows each)
    const int warpN = wid >> 1;          // 2 warps over N (64 cols each)

    // ldmatrix addressing: (row + 16*k) & 7 == row & 7, so XOR term is
    // constant across m/n subtiles — single base + inline stride.
    const int aRow0 = warpM * 64 + ((lane >> 3) & 1) * 8 + (lane & 7);
    const int aCh   = lane >> 4;           // chunk-half for A
    const int aRx   = aRow0 & 7;
    const uint32_t aBase0 = (uint32_t)(aRow0 * 128);

    const int bRow0 = warpN * 64 + (lane >> 4) * 8 + (lane & 7);
    const int bCh   = (lane >> 3) & 1;     // chunk-half for B
    const int bRx   = bRow0 & 7;
    const uint32_t bBase0 = (uint32_t)(bRow0 * 128);

    float c[4][8][4];
    #pragma unroll
    for (int i = 0; i < 4; i++)
        #pragma unroll
        for (int j = 0; j < 8; j++)
            #pragma unroll
            for (int k = 0; k < 4; k++) c[i][j][k] = 0.f;

    load_stage(smem_base, 0, 0, x, W, m0, n0, tid);

    #pragma unroll 1
    for (int kt = 0; kt < NCHUNK; ++kt) {
        asm volatile("cp.async.wait_group 0;" ::: "memory");
        __syncthreads();   // stage kt ready; all warps done with stage kt-1

        if (kt + 1 < NCHUNK)
            load_stage(smem_base, (kt + 1) & 1, kt + 1, x, W, m0, n0, tid);

        const uint32_t Ab  = smem_base + (kt & 1) * STAGE;
        const uint32_t Bbs = Ab + A_BYTES;
        #pragma unroll
        for (int ks = 0; ks < 4; ks++) {
            unsigned a[4][4];
            const uint32_t axor = (uint32_t)(((2 * ks + aCh) ^ aRx) << 4);
            #pragma unroll
            for (int mt = 0; mt < 4; mt++)
                LDSM_X4(a[mt], Ab + aBase0 + (uint32_t)(mt * 2048) + axor);
            const uint32_t bxor = (uint32_t)(((2 * ks + bCh) ^ bRx) << 4);
            #pragma unroll
            for (int j = 0; j < 4; j++) {
                unsigned b2[4];
                LDSM_X4(b2, Bbs + bBase0 + (uint32_t)(j * 2048) + bxor);
                #pragma unroll
                for (int mt = 0; mt < 4; mt++) {
                    MMA_TF32(c[mt][2 * j],     a[mt], (&b2[0]));
                    MMA_TF32(c[mt][2 * j + 1], a[mt], (&b2[2]));
                }
            }
        }
    }

    // epilogue: scatter with bias + pos + view fused
    const int group = lane >> 2;
    const int tig   = lane & 3;
    const int m_base = m0 + warpM * 64;
    const int n_base = n0 + warpN * 64;
    #pragma unroll
    for (int mt = 0; mt < 4; mt++) {
        #pragma unroll
        for (int rs = 0; rs < 2; rs++) {
            const int m   = m_base + mt * 16 + rs * 8 + group;
            const int bb  = m / Vv;
            const int tok = g_destTok[m];
            const float* prow = pos + tok * DEC;
            const float* vrow = ve + (tok >= Tt ? DEC : 0);
            float* optr = out + ((size_t)bb * TT + tok) * DEC;
            #pragma unroll
            for (int ni = 0; ni < 8; ni++) {
                const int n = n_base + ni * 8 + 2 * tig;
                float2 bp = *(const float2*)(bias + n);
                float2 pp = *(const float2*)(prow + n);
                float2 vv = *(const float2*)(vrow + n);
                float2 r;
                r.x = c[mt][ni][rs * 2 + 0] + bp.x + pp.x + vv.x;
                r.y = c[mt][ni][rs * 2 + 1] + bp.y + pp.y + vv.y;
                *(float2*)(optr + n) = r;
            }
        }
    }
}

// ============================================================
// launch
// ============================================================
extern "C" void kernel_launch(void* const* d_in, const int* in_sizes, int n_in,
                              void* d_out, int out_size) {
    const float* x          = (const float*)d_in[0];
    const void*  masked_ids = d_in[1];
    const float* W          = (const float*)d_in[2];
    const float* bias       = (const float*)d_in[3];
    const float* mask_token = (const float*)d_in[4];
    const float* pos        = (const float*)d_in[5];
    const float* ve         = (const float*)d_in[6];
    float* out = (float*)d_out;

    cudaFuncSetAttribute(fused_kernel,
                         cudaFuncAttributeMaxDynamicSharedMemorySize, SMEM_DYN);

    visids_kernel<<<Bb, 512>>>(masked_ids);
    fused_kernel<<<GEMMB + FILLB, NTHR, SMEM_DYN>>>(
        x, W, bias, mask_token, pos, ve, out);
}